// round 2
// baseline (speedup 1.0000x reference)
#include <cuda_runtime.h>
#include <cstdint>

#define NV 2048
#define NE 8192
#define D  128

// ---------------- device scratch (static: no runtime allocation) ----------------
__device__ __align__(16) float g_w[NE];                    // 32 KB
__device__ __align__(16) float g_Tw[(size_t)NV * NE];      // 64 MB  (tf32-rounded T*w)
__device__ __align__(16) float g_adjA[(size_t)NV * NV];    // 16 MB
__device__ __align__(16) float g_HW[NV * D];               // 1 MB

// ---------------- helpers ----------------
__device__ __forceinline__ uint32_t f2tf32(float x) {
    uint32_t u;
    asm("cvt.rna.tf32.f32 %0, %1;" : "=r"(u) : "f"(x));
    return u;
}

__device__ __forceinline__ void mma_tf32(float* d, const uint32_t* a, const uint32_t* b) {
    asm volatile(
        "mma.sync.aligned.m16n8k8.row.col.f32.tf32.tf32.f32 "
        "{%0,%1,%2,%3}, {%4,%5,%6,%7}, {%8,%9}, {%0,%1,%2,%3};\n"
        : "+f"(d[0]), "+f"(d[1]), "+f"(d[2]), "+f"(d[3])
        : "r"(a[0]), "r"(a[1]), "r"(a[2]), "r"(a[3]), "r"(b[0]), "r"(b[1]));
}

__device__ __forceinline__ void cp_async16(uint32_t saddr, const void* g) {
    asm volatile("cp.async.cg.shared.global [%0], [%1], 16;\n" :: "r"(saddr), "l"(g));
}
__device__ __forceinline__ void cp_commit() { asm volatile("cp.async.commit_group;\n" ::: "memory"); }
__device__ __forceinline__ void cp_wait0()  { asm volatile("cp.async.wait_group 0;\n" ::: "memory"); }

// ---------------- kernel 1: w = H_e @ p  (warp per row) ----------------
__global__ void k_w(const float* __restrict__ He, const float* __restrict__ p) {
    int row  = blockIdx.x * 8 + (threadIdx.x >> 5);
    int lane = threadIdx.x & 31;
    const float* r = He + (size_t)row * D;
    float s = 0.f;
#pragma unroll
    for (int j = 0; j < 4; j++) {
        int k = lane + 32 * j;
        s += r[k] * __ldg(p + k);
    }
#pragma unroll
    for (int o = 16; o > 0; o >>= 1) s += __shfl_xor_sync(0xffffffffu, s, o);
    if (lane == 0) g_w[row] = s;
}

// ---------------- kernel 2: Tw = round_tf32(T * w[col]) ----------------
__global__ void k_tw(const float* __restrict__ T) {
    size_t i4 = (size_t)blockIdx.x * blockDim.x + threadIdx.x;
    size_t e  = i4 * 4;
    int col = (int)(e & (size_t)(NE - 1));
    float4 t = *reinterpret_cast<const float4*>(T + e);
    float4 w = *reinterpret_cast<const float4*>(g_w + col);
    float4 o;
    o.x = __uint_as_float(f2tf32(t.x * w.x));
    o.y = __uint_as_float(f2tf32(t.y * w.y));
    o.z = __uint_as_float(f2tf32(t.z * w.z));
    o.w = __uint_as_float(f2tf32(t.w * w.w));
    *reinterpret_cast<float4*>(g_Tw + e) = o;
}

// ---------------- kernel 3: HW = H_v @ weight  (8 rows per block) ----------------
__global__ void k_hw(const float* __restrict__ Hv, const float* __restrict__ W) {
    __shared__ float sh[8][D];
    int r0  = blockIdx.x * 8;
    int tid = threadIdx.x;  // 128
#pragma unroll
    for (int r = 0; r < 8; r++) sh[r][tid] = Hv[(size_t)(r0 + r) * D + tid];
    __syncthreads();
    float acc[8] = {};
    for (int k = 0; k < D; k++) {
        float wk = W[k * D + tid];
#pragma unroll
        for (int r = 0; r < 8; r++) acc[r] += sh[r][k] * wk;
    }
#pragma unroll
    for (int r = 0; r < 8; r++) g_HW[(r0 + r) * D + tid] = acc[r];
}

// ---------------- kernel 4: big symmetric GEMM + mask epilogue ----------------
// C = Tw @ T^T  (2048x2048, K=8192), only upper-tri 128x128 blocks computed.
// Epilogue: adjA[i][j] = ((i==j)?1:C[i][j]) * adj_v[i][j]   (+ mirrored block)
#define BM 128
#define BK 32
#define ASTRIDE (BK + 4)                 // 36 floats -> conflict-free frag loads
#define STAGE_FLOATS (2 * BM * ASTRIDE)  // A + B tile per stage = 9216 floats
#define SMEM_BYTES (2 * STAGE_FLOATS * 4)  // 73728 B

__global__ void __launch_bounds__(256, 1)
k_gemm1(const float* __restrict__ T, const float* __restrict__ adj_v) {
    // decode upper-triangular block index (16x16 grid of 128-blocks)
    int l = blockIdx.x, bm = 0, rem = 16;
    while (l >= rem) { l -= rem; bm++; rem--; }
    int bn = bm + l;

    extern __shared__ float smem[];
    uint32_t sbase = (uint32_t)__cvta_generic_to_shared(smem);

    int tid  = threadIdx.x;
    int warp = tid >> 5, lane = tid & 31;
    int wm = warp & 3, wn = warp >> 2;     // 4x2 warp grid: warp = 32 rows x 64 cols
    int gid = lane >> 2, tig = lane & 3;

    const float* gA = g_Tw + (size_t)(bm * BM) * NE;
    const float* gB = T    + (size_t)(bn * BM) * NE;

    float acc[2][8][4];
#pragma unroll
    for (int m = 0; m < 2; m++)
#pragma unroll
        for (int n = 0; n < 8; n++)
#pragma unroll
            for (int q = 0; q < 4; q++) acc[m][n][q] = 0.f;

    const int nkt = NE / BK;  // 256

    // tile loader: 128 rows x 32 floats per operand; 1024 16B-chunks over 256 threads (4 each)
    auto load_stage = [&](int s, int kt) {
        uint32_t sA = sbase + (uint32_t)(s * STAGE_FLOATS) * 4u;
        uint32_t sB = sA + (uint32_t)(BM * ASTRIDE) * 4u;
#pragma unroll
        for (int i = 0; i < 4; i++) {
            int c = i * 256 + tid;
            int row = c >> 3, c16 = c & 7;
            uint32_t soff = (uint32_t)(row * ASTRIDE + c16 * 4) * 4u;
            cp_async16(sA + soff, gA + (size_t)row * NE + kt * BK + c16 * 4);
            cp_async16(sB + soff, gB + (size_t)row * NE + kt * BK + c16 * 4);
        }
    };

    load_stage(0, 0);
    cp_commit();

    for (int kt = 0; kt < nkt; kt++) {
        cp_wait0();
        __syncthreads();
        int s = kt & 1;
        if (kt + 1 < nkt) { load_stage(s ^ 1, kt + 1); cp_commit(); }

        const float* As = smem + s * STAGE_FLOATS;
        const float* Bs = As + BM * ASTRIDE;
#pragma unroll
        for (int ks = 0; ks < 4; ks++) {
            int k0 = ks * 8;
            uint32_t af[2][4], bf[8][2];
#pragma unroll
            for (int m = 0; m < 2; m++) {
                const float* ap = As + (wm * 32 + m * 16 + gid) * ASTRIDE + k0 + tig;
                af[m][0] = __float_as_uint(ap[0]);             // Tw already tf32-rounded
                af[m][1] = __float_as_uint(ap[8 * ASTRIDE]);
                af[m][2] = __float_as_uint(ap[4]);
                af[m][3] = __float_as_uint(ap[8 * ASTRIDE + 4]);
            }
#pragma unroll
            for (int n = 0; n < 8; n++) {
                const float* bp = Bs + (wn * 64 + n * 8 + gid) * ASTRIDE + k0 + tig;
                bf[n][0] = f2tf32(bp[0]);
                bf[n][1] = f2tf32(bp[4]);
            }
#pragma unroll
            for (int m = 0; m < 2; m++)
#pragma unroll
                for (int n = 0; n < 8; n++) mma_tf32(acc[m][n], af[m], bf[n]);
        }
    }

    // epilogue: mask + adj_v multiply; mirror into (bn,bm) block when off-diagonal
    bool offdiag = (bm != bn);
#pragma unroll
    for (int m = 0; m < 2; m++) {
        int i0 = bm * BM + wm * 32 + m * 16 + gid;
#pragma unroll
        for (int n = 0; n < 8; n++) {
            int j0 = bn * BM + wn * 64 + n * 8 + 2 * tig;
#pragma unroll
            for (int q = 0; q < 4; q++) {
                int i = i0 + (q >> 1) * 8;
                int j = j0 + (q & 1);
                float v = acc[m][n][q];
                float m1 = (i == j) ? 1.0f : v;
                g_adjA[(size_t)i * NV + j] = m1 * adj_v[(size_t)i * NV + j];
                if (offdiag)  // i != j guaranteed
                    g_adjA[(size_t)j * NV + i] = v * adj_v[(size_t)j * NV + i];
            }
        }
    }
}

// ---------------- kernel 5: ret = adjA @ HW + bias (fp32 SIMT) ----------------
__global__ void __launch_bounds__(256)
k_gemm2(const float* __restrict__ bias, float* __restrict__ out) {
    __shared__ float sa[16][33];
    int tid  = threadIdx.x;       // 256
    int col  = tid & 127;
    int half = tid >> 7;
    int r0   = blockIdx.x * 16;
    float acc[8] = {};
    for (int kt = 0; kt < NV / 32; kt++) {
        __syncthreads();
#pragma unroll
        for (int i = 0; i < 2; i++) {
            int c = i * 256 + tid;
            int r = c >> 5, k = c & 31;
            sa[r][k] = g_adjA[(size_t)(r0 + r) * NV + kt * 32 + k];
        }
        __syncthreads();
#pragma unroll 8
        for (int k = 0; k < 32; k++) {
            float hw = g_HW[(kt * 32 + k) * D + col];
#pragma unroll
            for (int r = 0; r < 8; r++) acc[r] += sa[half * 8 + r][k] * hw;
        }
    }
    float b = bias[col];
#pragma unroll
    for (int r = 0; r < 8; r++)
        out[(size_t)(r0 + half * 8 + r) * D + col] = acc[r] + b;
}

// ---------------- launch ----------------
extern "C" void kernel_launch(void* const* d_in, const int* in_sizes, int n_in,
                              void* d_out, int out_size) {
    const float* H_v   = (const float*)d_in[0];
    const float* H_e   = (const float*)d_in[1];
    // d_in[2] = adj_e : UNUSED by the reference graph (node_layer branch)
    const float* adj_v = (const float*)d_in[3];
    const float* T     = (const float*)d_in[4];
    const float* W     = (const float*)d_in[5];
    const float* p     = (const float*)d_in[6];
    const float* bias  = (const float*)d_in[7];
    float* out = (float*)d_out;

    k_w<<<NE / 8, 256>>>(H_e, p);
    k_tw<<<(NV * NE / 4) / 256, 256>>>(T);
    k_hw<<<NV / 8, 128>>>(H_v, W);

    cudaFuncSetAttribute(k_gemm1, cudaFuncAttributeMaxDynamicSharedMemorySize, SMEM_BYTES);
    k_gemm1<<<136, 256, SMEM_BYTES>>>(T, adj_v);

    k_gemm2<<<NV / 16, 256>>>(bias, out);

    // second output: H_e passthrough, concatenated after ret
    if (out_size >= NV * D + NE * D) {
        cudaMemcpyAsync(out + NV * D, H_e, (size_t)NE * D * sizeof(float),
                        cudaMemcpyDeviceToDevice, 0);
    }
}

// round 3
// speedup vs baseline: 1.0300x; 1.0300x over previous
#include <cuda_runtime.h>
#include <cstdint>

#define NV 2048
#define NE 8192
#define D  128

// ---------------- device scratch (static: no runtime allocation) ----------------
__device__ __align__(16) float g_w[NE];                    // 32 KB
__device__ __align__(16) float g_Tw[(size_t)NV * NE];      // 64 MB  tf32(T*w)
__device__ __align__(16) float g_Ttf[(size_t)NV * NE];     // 64 MB  tf32(T)
__device__ __align__(16) float g_adjA[(size_t)NV * NV];    // 16 MB
__device__ __align__(16) float g_HW[NV * D];               // 1 MB

// ---------------- helpers ----------------
__device__ __forceinline__ uint32_t f2tf32(float x) {
    uint32_t u;
    asm("cvt.rna.tf32.f32 %0, %1;" : "=r"(u) : "f"(x));
    return u;
}

__device__ __forceinline__ void mma_tf32(float* d, const uint32_t* a, const uint32_t* b) {
    asm volatile(
        "mma.sync.aligned.m16n8k8.row.col.f32.tf32.tf32.f32 "
        "{%0,%1,%2,%3}, {%4,%5,%6,%7}, {%8,%9}, {%0,%1,%2,%3};\n"
        : "+f"(d[0]), "+f"(d[1]), "+f"(d[2]), "+f"(d[3])
        : "r"(a[0]), "r"(a[1]), "r"(a[2]), "r"(a[3]), "r"(b[0]), "r"(b[1]));
}

__device__ __forceinline__ void cp_async16(uint32_t saddr, const void* g) {
    asm volatile("cp.async.cg.shared.global [%0], [%1], 16;\n" :: "r"(saddr), "l"(g));
}
__device__ __forceinline__ void cp_commit() { asm volatile("cp.async.commit_group;\n" ::: "memory"); }
__device__ __forceinline__ void cp_wait1()  { asm volatile("cp.async.wait_group 1;\n" ::: "memory"); }

// ---------------- kernel 1: w = H_e @ p  (warp per row) ----------------
__global__ void k_w(const float* __restrict__ He, const float* __restrict__ p) {
    int row  = blockIdx.x * 8 + (threadIdx.x >> 5);
    int lane = threadIdx.x & 31;
    const float* r = He + (size_t)row * D;
    float s = 0.f;
#pragma unroll
    for (int j = 0; j < 4; j++) {
        int k = lane + 32 * j;
        s += r[k] * __ldg(p + k);
    }
#pragma unroll
    for (int o = 16; o > 0; o >>= 1) s += __shfl_xor_sync(0xffffffffu, s, o);
    if (lane == 0) g_w[row] = s;
}

// ---------------- kernel 2: Tw = tf32(T*w), Ttf = tf32(T)  (one read of T) ----------------
__global__ void k_prep(const float* __restrict__ T) {
    size_t i4 = (size_t)blockIdx.x * blockDim.x + threadIdx.x;
    size_t e  = i4 * 4;
    int col = (int)(e & (size_t)(NE - 1));
    float4 t = *reinterpret_cast<const float4*>(T + e);
    float4 w = *reinterpret_cast<const float4*>(g_w + col);
    float4 o, r;
    o.x = __uint_as_float(f2tf32(t.x * w.x));
    o.y = __uint_as_float(f2tf32(t.y * w.y));
    o.z = __uint_as_float(f2tf32(t.z * w.z));
    o.w = __uint_as_float(f2tf32(t.w * w.w));
    r.x = __uint_as_float(f2tf32(t.x));
    r.y = __uint_as_float(f2tf32(t.y));
    r.z = __uint_as_float(f2tf32(t.z));
    r.w = __uint_as_float(f2tf32(t.w));
    *reinterpret_cast<float4*>(g_Tw + e)  = o;
    *reinterpret_cast<float4*>(g_Ttf + e) = r;
}

// ---------------- kernel 3: HW = H_v @ weight  (8 rows per block) ----------------
__global__ void k_hw(const float* __restrict__ Hv, const float* __restrict__ W) {
    __shared__ float sh[8][D];
    int r0  = blockIdx.x * 8;
    int tid = threadIdx.x;  // 128
#pragma unroll
    for (int r = 0; r < 8; r++) sh[r][tid] = Hv[(size_t)(r0 + r) * D + tid];
    __syncthreads();
    float acc[8] = {};
    for (int k = 0; k < D; k++) {
        float wk = W[k * D + tid];
#pragma unroll
        for (int r = 0; r < 8; r++) acc[r] += sh[r][k] * wk;
    }
#pragma unroll
    for (int r = 0; r < 8; r++) g_HW[(r0 + r) * D + tid] = acc[r];
}

// ---------------- kernel 4: big symmetric GEMM + mask epilogue ----------------
// C = Tw @ Ttf^T  (2048x2048, K=8192), only upper-tri 128x128 blocks computed.
// Epilogue: adjA[i][j] = ((i==j)?1:C[i][j]) * adj_v[i][j]   (+ mirrored block)
#define BM 128
#define BK 32
#define ASTRIDE (BK + 4)                 // 36 floats -> conflict-free LDS.32 frag loads
#define STAGE_FLOATS (2 * BM * ASTRIDE)  // A + B tile per stage = 9216 floats
#define NSTAGE 3
#define SMEM_BYTES (NSTAGE * STAGE_FLOATS * 4)  // 110592 B

__global__ void __launch_bounds__(256, 1)
k_gemm1(const float* __restrict__ adj_v) {
    // decode upper-triangular block index (16x16 grid of 128-blocks)
    int l = blockIdx.x, bm = 0, rem = 16;
    while (l >= rem) { l -= rem; bm++; rem--; }
    int bn = bm + l;

    extern __shared__ float smem[];
    uint32_t sbase = (uint32_t)__cvta_generic_to_shared(smem);

    int tid  = threadIdx.x;
    int warp = tid >> 5, lane = tid & 31;
    int wm = warp & 3, wn = warp >> 2;     // 4x2 warp grid: warp = 32 rows x 64 cols
    int gid = lane >> 2, tig = lane & 3;

    const float* gA = g_Tw  + (size_t)(bm * BM) * NE;
    const float* gB = g_Ttf + (size_t)(bn * BM) * NE;

    float acc[2][8][4];
#pragma unroll
    for (int m = 0; m < 2; m++)
#pragma unroll
        for (int n = 0; n < 8; n++)
#pragma unroll
            for (int q = 0; q < 4; q++) acc[m][n][q] = 0.f;

    const int nkt = NE / BK;  // 256

    // tile loader: 128 rows x 32 floats per operand; 1024 16B-chunks over 256 threads
    auto load_stage = [&](int s, int kt) {
        uint32_t sA = sbase + (uint32_t)(s * STAGE_FLOATS) * 4u;
        uint32_t sB = sA + (uint32_t)(BM * ASTRIDE) * 4u;
#pragma unroll
        for (int i = 0; i < 4; i++) {
            int c = i * 256 + tid;
            int row = c >> 3, c16 = c & 7;
            uint32_t soff = (uint32_t)(row * ASTRIDE + c16 * 4) * 4u;
            cp_async16(sA + soff, gA + (size_t)row * NE + kt * BK + c16 * 4);
            cp_async16(sB + soff, gB + (size_t)row * NE + kt * BK + c16 * 4);
        }
    };

    load_stage(0, 0); cp_commit();
    load_stage(1, 1); cp_commit();

    // per-warp base offsets into a stage (in floats)
    int aRow = wm * 32 + gid;
    int bRow = wn * 64 + gid;

    for (int kt = 0; kt < nkt; kt++) {
        cp_wait1();            // stage (kt % NSTAGE) ready
        __syncthreads();
        int s = kt % NSTAGE;
        if (kt + 2 < nkt) { load_stage((kt + 2) % NSTAGE, kt + 2); cp_commit(); }

        const float* As = smem + s * STAGE_FLOATS;
        const float* Bs = As + BM * ASTRIDE;
        const float* apBase = As + aRow * ASTRIDE + tig;
        const float* bpBase = Bs + bRow * ASTRIDE + tig;

        uint32_t af[2][2][4], bf[2][8][2];

        // fragment loader for one ks into buffer `buf`
        auto ldfrag = [&](int buf, int ks) {
            int k0 = ks * 8;
#pragma unroll
            for (int m = 0; m < 2; m++) {
                const uint32_t* ap = reinterpret_cast<const uint32_t*>(apBase + m * 16 * ASTRIDE + k0);
                af[buf][m][0] = ap[0];
                af[buf][m][1] = ap[8 * ASTRIDE];
                af[buf][m][2] = ap[4];
                af[buf][m][3] = ap[8 * ASTRIDE + 4];
            }
#pragma unroll
            for (int n = 0; n < 8; n++) {
                const uint32_t* bp = reinterpret_cast<const uint32_t*>(bpBase + n * 8 * ASTRIDE + k0);
                bf[buf][n][0] = bp[0];
                bf[buf][n][1] = bp[4];
            }
        };

        ldfrag(0, 0);
#pragma unroll
        for (int ks = 0; ks < 4; ks++) {
            if (ks < 3) ldfrag((ks + 1) & 1, ks + 1);   // prefetch next frags
            int b = ks & 1;
#pragma unroll
            for (int m = 0; m < 2; m++)
#pragma unroll
                for (int n = 0; n < 8; n++) mma_tf32(acc[m][n], af[b][m], bf[b][n]);
        }
    }

    // epilogue: mask + adj_v multiply; mirror into (bn,bm) block when off-diagonal
    bool offdiag = (bm != bn);
#pragma unroll
    for (int m = 0; m < 2; m++) {
        int i0 = bm * BM + wm * 32 + m * 16 + gid;
#pragma unroll
        for (int n = 0; n < 8; n++) {
            int j0 = bn * BM + wn * 64 + n * 8 + 2 * tig;
#pragma unroll
            for (int q = 0; q < 4; q++) {
                int i = i0 + (q >> 1) * 8;
                int j = j0 + (q & 1);
                float v = acc[m][n][q];
                float m1 = (i == j) ? 1.0f : v;
                g_adjA[(size_t)i * NV + j] = m1 * adj_v[(size_t)i * NV + j];
                if (offdiag)  // i != j guaranteed
                    g_adjA[(size_t)j * NV + i] = v * adj_v[(size_t)j * NV + i];
            }
        }
    }
}

// ---------------- kernel 5: ret = adjA @ HW + bias (fp32 SIMT) ----------------
__global__ void __launch_bounds__(256)
k_gemm2(const float* __restrict__ bias, float* __restrict__ out) {
    __shared__ float sa[16][33];
    int tid  = threadIdx.x;       // 256
    int col  = tid & 127;
    int half = tid >> 7;
    int r0   = blockIdx.x * 16;
    float acc[8] = {};
    for (int kt = 0; kt < NV / 32; kt++) {
        __syncthreads();
#pragma unroll
        for (int i = 0; i < 2; i++) {
            int c = i * 256 + tid;
            int r = c >> 5, k = c & 31;
            sa[r][k] = g_adjA[(size_t)(r0 + r) * NV + kt * 32 + k];
        }
        __syncthreads();
#pragma unroll 8
        for (int k = 0; k < 32; k++) {
            float hw = g_HW[(kt * 32 + k) * D + col];
#pragma unroll
            for (int r = 0; r < 8; r++) acc[r] += sa[half * 8 + r][k] * hw;
        }
    }
    float b = bias[col];
#pragma unroll
    for (int r = 0; r < 8; r++)
        out[(size_t)(r0 + half * 8 + r) * D + col] = acc[r] + b;
}

// ---------------- launch ----------------
extern "C" void kernel_launch(void* const* d_in, const int* in_sizes, int n_in,
                              void* d_out, int out_size) {
    const float* H_v   = (const float*)d_in[0];
    const float* H_e   = (const float*)d_in[1];
    // d_in[2] = adj_e : UNUSED by the reference graph (node_layer branch)
    const float* adj_v = (const float*)d_in[3];
    const float* T     = (const float*)d_in[4];
    const float* W     = (const float*)d_in[5];
    const float* p     = (const float*)d_in[6];
    const float* bias  = (const float*)d_in[7];
    float* out = (float*)d_out;

    k_w<<<NE / 8, 256>>>(H_e, p);
    k_prep<<<(NV * NE / 4) / 256, 256>>>(T);
    k_hw<<<NV / 8, 128>>>(H_v, W);

    cudaFuncSetAttribute(k_gemm1, cudaFuncAttributeMaxDynamicSharedMemorySize, SMEM_BYTES);
    k_gemm1<<<136, 256, SMEM_BYTES>>>(adj_v);

    k_gemm2<<<NV / 16, 256>>>(bias, out);

    // second output: H_e passthrough, concatenated after ret
    if (out_size >= NV * D + NE * D) {
        cudaMemcpyAsync(out + NV * D, H_e, (size_t)NE * D * sizeof(float),
                        cudaMemcpyDeviceToDevice, 0);
    }
}